// round 6
// baseline (speedup 1.0000x reference)
#include <cuda_runtime.h>

#define NQ 900
#define NB 32
#define NC 91
#define TBTH 0.9f

// ---- fill: 9 contiguous adj rows per CTA (R1 kwrite pattern), diag baked ----
#define ROWS_PER_FILL 9
#define FILL_BLOCKS (NB * NQ / ROWS_PER_FILL)   // 3200

// ---- logits copy ----
#define COPY_BLOCKS 640
#define LOG_F4 (NB * NQ * NC / 4)               // 655,200

// ---- GIoU ----
#define GB_PER_BATCH 15
#define RPB 30                                  // 450/30 = 15 blocks per batch
#define GIOU_BLOCKS (NB * GB_PER_BATCH)         // 480
#define ECAP 256

#define K_BLOCKS (FILL_BLOCKS + COPY_BLOCKS + GIOU_BLOCKS)   // 4320

#define LOG_OFF_F (NB * NQ * 4)                 // 115,200
#define ADJ_OFF_F (LOG_OFF_F + NB * NQ * NC)    // 2,736,000

#define MAXE 1024
#define MAXM 256

// device scratch (allocation-free; counters zero at load, self-reset each call)
__device__ unsigned int g_bedge[GIOU_BLOCKS * ECAP];
__device__ int g_bcnt[GIOU_BLOCKS];
__device__ int g_done[NB];
__device__ int g_fill_done;
__device__ int g_patch;

__global__ void __launch_bounds__(256) kall(const float4* __restrict__ bboxes,
                                            const float4* __restrict__ logits,
                                            float* __restrict__ out) {
    __shared__ __align__(16) unsigned char sbuf[28800];
    __shared__ int s_cnt, s_changed, s_nm, s_last;

    const int u = blockIdx.x;
    const int tid = threadIdx.x;

    if (u < FILL_BLOCKS) {
        // ---------- adj zero-fill with baked diagonal: R1 kwrite store pattern ----------
        float4* adj4 = (float4*)(out + ADJ_OFF_F);
        const int row0 = u * ROWS_PER_FILL;
        #pragma unroll
        for (int r = 0; r < ROWS_PER_FILL; r++) {
            const int grow = row0 + r;           // flattened row b*900+i
            const int i = grow % NQ;
            const int dc = i >> 2, dl = i & 3;
            float4* dst = adj4 + (size_t)grow * (NQ / 4);
            for (int c = tid; c < NQ / 4; c += 256) {
                float4 v = make_float4(0.f, 0.f, 0.f, 0.f);
                if (c == dc) ((float*)&v)[dl] = 1.0f;
                dst[c] = v;
            }
        }
        __threadfence();
        __syncthreads();
        if (tid == 0) atomicAdd(&g_fill_done, 1);
        return;
    }

    if (u < FILL_BLOCKS + COPY_BLOCKS) {
        // ---------- logits pass-through ----------
        const int cu = u - FILL_BLOCKS;
        float4* dst = (float4*)(out + LOG_OFF_F);
        const int stride = COPY_BLOCKS * 256;
        int idx = cu * 256 + tid;
        #pragma unroll
        for (int rep = 0; rep < 4; rep++) {
            if (idx < LOG_F4) dst[idx] = __ldcs(&logits[idx]);
            idx += stride;
        }
        return;
    }

    // ---------------- GIoU edge detection ----------------
    {
        float* sx1 = (float*)(sbuf + 0);
        float* sy1 = (float*)(sbuf + 3600);
        float* sx2 = (float*)(sbuf + 7200);
        float* sy2 = (float*)(sbuf + 10800);
        float* sa  = (float*)(sbuf + 14400);

        const int g = u - FILL_BLOCKS - COPY_BLOCKS;
        const int b = g / GB_PER_BATCH;
        const int blk = g % GB_PER_BATCH;
        if (tid == 0) { s_cnt = 0; s_nm = 0; }

        for (int i = tid; i < NQ; i += 256) {
            float4 bb = bboxes[b * NQ + i];
            float hw = 0.5f * bb.z, hh = 0.5f * bb.w;
            float x1 = bb.x - hw, y1 = bb.y - hh;
            float x2 = bb.x + hw, y2 = bb.y + hh;
            sx1[i] = x1; sy1[i] = y1; sx2[i] = x2; sy2[i] = y2;
            sa[i]  = (x2 - x1) * (y2 - y1);
        }
        __syncthreads();

        const int rp0 = blk * RPB;
        for (int rp = rp0; rp < rp0 + RPB; rp++) {
            #pragma unroll
            for (int half = 0; half < 2; half++) {
                int i = half ? (898 - rp) : rp;
                if (half && i == rp) break;
                const float x1i = sx1[i], y1i = sy1[i];
                const float x2i = sx2[i], y2i = sy2[i];
                const float ai  = sa[i];
                for (int j = i + 1 + tid; j < NQ; j += 256) {
                    float aj = sa[j];
                    float mn = fminf(ai, aj), mx = fmaxf(ai, aj);
                    if (mn < 0.8999f * mx) continue;   // giou <= iou <= min/max area
                    float wi = fminf(x2i, sx2[j]) - fmaxf(x1i, sx1[j]);
                    if (wi <= 0.0f) continue;
                    float hi = fminf(y2i, sy2[j]) - fmaxf(y1i, sy1[j]);
                    if (hi <= 0.0f) continue;
                    float inter = wi * hi;
                    float uni   = ai + aj - inter;
                    float we = fmaxf(x2i, sx2[j]) - fminf(x1i, sx1[j]);
                    float he = fmaxf(y2i, sy2[j]) - fminf(y1i, sy1[j]);
                    float ae = we * he;
                    float gf = __fdividef(inter, uni) - __fdividef(ae - uni, ae);
                    bool edge;
                    if (fabsf(gf - TBTH) > 3e-4f) {
                        edge = gf > TBTH;
                    } else {
                        float iou = inter / uni;       // bit-exact reference sequence
                        float q   = (ae - uni) / ae;
                        edge = (iou - q) > TBTH;
                    }
                    if (edge) {
                        int p = atomicAdd(&s_cnt, 1);
                        if (p < ECAP)
                            g_bedge[g * ECAP + p] = ((unsigned)i << 10) | (unsigned)j;
                    }
                }
            }
        }
        __threadfence();
        __syncthreads();
        if (tid == 0) {
            g_bcnt[g] = min(s_cnt, ECAP);
            __threadfence();
            int t = atomicAdd(&g_done[b], 1);
            s_last = (t == GB_PER_BATCH - 1);
            if (s_last) g_done[b] = 0;      // reset for next replay
        }
        __syncthreads();
        if (!s_last) return;

        // -------- last block of batch: gather edges, CC, aggregation --------
        __threadfence();   // acquire: all batch edge data visible
        int*   lab   = (int*)(sbuf + 0);                       // 3600
        float* csum  = (float*)(sbuf + 3600);                  // 14400
        float* ccnt  = (float*)(sbuf + 18000);                 // 3600
        unsigned int* sedge = (unsigned int*)(sbuf + 21600);   // 4096
        short* mlist = (short*)(sbuf + 25696);                 // 512
        int*   scnt  = (int*)(sbuf + 26208);                   // counts + offsets
        int*   coff  = scnt + GB_PER_BATCH;

        for (int i = tid; i < NQ; i += 256) lab[i] = i;
        if (tid < GB_PER_BATCH) scnt[tid] = g_bcnt[b * GB_PER_BATCH + tid];
        __syncthreads();
        if (tid == 0) {
            int s = 0;
            #pragma unroll
            for (int k = 0; k < GB_PER_BATCH; k++) { coff[k] = s; s += scnt[k]; }
            coff[GB_PER_BATCH] = s;
        }
        __syncthreads();
        const int ne = min(coff[GB_PER_BATCH], MAXE);

        for (int e = tid; e < ne; e += 256) {
            int k = 0;
            #pragma unroll
            for (int t2 = 0; t2 < GB_PER_BATCH; t2++)
                if (e >= coff[t2 + 1]) k = t2 + 1;
            sedge[e] = g_bedge[(b * GB_PER_BATCH + k) * ECAP + (e - coff[k])];
        }
        __syncthreads();

        for (int it = 0; it < NQ; it++) {
            if (tid == 0) s_changed = 0;
            __syncthreads();
            for (int e = tid; e < ne; e += 256) {
                unsigned int pk = sedge[e];
                int i = pk >> 10, j = pk & 1023;
                int li = lab[i], lj = lab[j];
                int m = min(li, lj);
                if (li > m) { atomicMin(&lab[i], m); s_changed = 1; }
                if (lj > m) { atomicMin(&lab[j], m); s_changed = 1; }
            }
            __syncthreads();
            for (int i = tid; i < NQ; i += 256) {
                int l = lab[i], ll = lab[l];
                if (ll < l) { lab[i] = ll; s_changed = 1; }
            }
            __syncthreads();
            int ch = s_changed;
            __syncthreads();
            if (!ch) break;
        }

        for (int i = tid; i < NQ; i += 256) {
            ccnt[i] = 0.0f;
            csum[4 * i + 0] = 0.0f; csum[4 * i + 1] = 0.0f;
            csum[4 * i + 2] = 0.0f; csum[4 * i + 3] = 0.0f;
        }
        __syncthreads();
        for (int i = tid; i < NQ; i += 256) {
            int l = lab[i];
            float4 bb = bboxes[b * NQ + i];
            atomicAdd(&ccnt[l], 1.0f);
            atomicAdd(&csum[4 * l + 0], bb.x);
            atomicAdd(&csum[4 * l + 1], bb.y);
            atomicAdd(&csum[4 * l + 2], bb.z);
            atomicAdd(&csum[4 * l + 3], bb.w);
        }
        __syncthreads();

        float4* oagg = (float4*)out;
        for (int i = tid; i < NQ; i += 256) {
            int l = lab[i];
            float d = ccnt[l] + 1e-6f;
            float4 o;
            o.x = csum[4 * l + 0] / d;
            o.y = csum[4 * l + 1] / d;
            o.z = csum[4 * l + 2] / d;
            o.w = csum[4 * l + 3] / d;
            oagg[b * NQ + i] = o;
            if (ccnt[l] > 1.5f) {
                int p = atomicAdd(&s_nm, 1);
                if (p < MAXM) mlist[p] = (short)i;
            }
        }
        __syncthreads();
        const int nm = min(s_nm, MAXM);

        // -------- wait for adj fill, then patch off-diagonal 1.0s --------
        if (tid == 0) {
            while (atomicAdd(&g_fill_done, 0) < FILL_BLOCKS) __nanosleep(200);
        }
        __syncthreads();
        __threadfence();   // order patches after observed fill completion

        float* adj = out + ADJ_OFF_F;
        for (int p = tid; p < nm * nm; p += 256) {
            int a = mlist[p / nm];
            int c = mlist[p % nm];
            if (a != c && lab[a] == lab[c])
                adj[((size_t)(b * NQ + a)) * NQ + c] = 1.0f;
        }
        __threadfence();
        __syncthreads();
        if (tid == 0) {
            int t = atomicAdd(&g_patch, 1);
            if (t == NB - 1) {              // last patcher resets for next replay
                g_patch = 0;
                g_fill_done = 0;
                __threadfence();
            }
        }
    }
}

extern "C" void kernel_launch(void* const* d_in, const int* in_sizes, int n_in,
                              void* d_out, int out_size) {
    const float4* bboxes = (const float4*)d_in[0];   // [32,900,4] fp32
    const float4* logits = (const float4*)d_in[1];   // [32,900,91] fp32
    float* out = (float*)d_out;                      // agg | logits | adj

    kall<<<K_BLOCKS, 256>>>(bboxes, logits, out);
}

// round 7
// speedup vs baseline: 1.7490x; 1.7490x over previous
#include <cuda_runtime.h>

#define NQ 900
#define NB 32
#define NC 91
#define TBTH 0.9f

// ---- K1 block-range layout (R3 ordering: giou first, fill, copy) ----
#define GB_PER_BATCH 25
#define RPB 18                 // 450/18 = 25 blocks per batch
#define GIOU_BLOCKS (NB * GB_PER_BATCH)   // 800
#define ECAP 256

#define FILL_BLOCKS 3200
#define COPY_BLOCKS 640
#define K1_BLOCKS (GIOU_BLOCKS + FILL_BLOCKS + COPY_BLOCKS)  // 4640

#define ADJ_F4 (NB * NQ * (NQ / 4))        // 6,480,000 float4
#define LOG_F4 (NB * NQ * NC / 4)          // 655,200 float4

#define LOG_OFF_F (NB * NQ * 4)            // 115,200
#define ADJ_OFF_F (LOG_OFF_F + NB * NQ * NC)

#define MAXE 1024
#define MAXM 256

// device scratch (allocation-free; g_done zero at load, self-resets each call)
__device__ unsigned int g_bedge[GIOU_BLOCKS * ECAP];
__device__ int g_bcnt[GIOU_BLOCKS];
__device__ int g_done[NB];
__device__ int g_labels[NB * NQ];
__device__ int g_mlist[NB * MAXM];
__device__ int g_nm[NB];

// ======================= K1: giou(+fused CC) | adj zero stream | logits copy =======================
__global__ void __launch_bounds__(256) k1(const float4* __restrict__ bboxes,
                                          const float4* __restrict__ logits,
                                          float* __restrict__ out) {
    __shared__ __align__(16) unsigned char sbuf[22400];
    __shared__ int s_cnt, s_changed, s_nm, s_last;

    const int u = blockIdx.x;
    const int tid = threadIdx.x;

    if (u >= GIOU_BLOCKS && u < GIOU_BLOCKS + FILL_BLOCKS) {
        // ---------- adj zero-fill: R3 pattern verbatim (grid-stride __stcs, no fences) ----------
        float4* adj = (float4*)(out + ADJ_OFF_F);
        const float4 z = make_float4(0.f, 0.f, 0.f, 0.f);
        const long long stride = (long long)FILL_BLOCKS * 256;
        long long idx = (long long)(u - GIOU_BLOCKS) * 256 + tid;
        #pragma unroll
        for (int rep = 0; rep < 2; rep++) {
            long long i0 = idx, i1 = idx + stride, i2 = idx + 2 * stride, i3 = idx + 3 * stride;
            if (i0 < ADJ_F4) __stcs(&adj[i0], z);
            if (i1 < ADJ_F4) __stcs(&adj[i1], z);
            if (i2 < ADJ_F4) __stcs(&adj[i2], z);
            if (i3 < ADJ_F4) __stcs(&adj[i3], z);
            idx += 4 * stride;
        }
        return;
    }

    if (u >= GIOU_BLOCKS) {
        // ---------- logits pass-through: R3 pattern verbatim ----------
        const int cu = u - GIOU_BLOCKS - FILL_BLOCKS;
        float4* dst = (float4*)(out + LOG_OFF_F);
        const int stride = COPY_BLOCKS * 256;
        int idx = cu * 256 + tid;
        #pragma unroll
        for (int rep = 0; rep < 4; rep++) {
            if (idx < LOG_F4) __stcs(&dst[idx], __ldcs(&logits[idx]));
            idx += stride;
        }
        return;
    }

    // ---------------- GIoU edge detection ----------------
    {
        float* sx1 = (float*)(sbuf + 0);
        float* sy1 = (float*)(sbuf + 3600);
        float* sx2 = (float*)(sbuf + 7200);
        float* sy2 = (float*)(sbuf + 10800);
        float* sa  = (float*)(sbuf + 14400);

        const int b = u / GB_PER_BATCH;
        const int blk = u % GB_PER_BATCH;
        if (tid == 0) { s_cnt = 0; s_nm = 0; }

        for (int i = tid; i < NQ; i += 256) {
            float4 bb = bboxes[b * NQ + i];
            float hw = 0.5f * bb.z, hh = 0.5f * bb.w;
            float x1 = bb.x - hw, y1 = bb.y - hh;
            float x2 = bb.x + hw, y2 = bb.y + hh;
            sx1[i] = x1; sy1[i] = y1; sx2[i] = x2; sy2[i] = y2;
            sa[i]  = (x2 - x1) * (y2 - y1);
        }
        __syncthreads();

        const int rp0 = blk * RPB;
        for (int rp = rp0; rp < rp0 + RPB; rp++) {
            #pragma unroll
            for (int half = 0; half < 2; half++) {
                int i = half ? (898 - rp) : rp;
                if (half && i == rp) break;
                const float x1i = sx1[i], y1i = sy1[i];
                const float x2i = sx2[i], y2i = sy2[i];
                const float ai  = sa[i];
                for (int j = i + 1 + tid; j < NQ; j += 256) {
                    float aj = sa[j];
                    float mn = fminf(ai, aj), mx = fmaxf(ai, aj);
                    if (mn < 0.8999f * mx) continue;   // giou <= iou <= min/max area
                    float wi = fminf(x2i, sx2[j]) - fmaxf(x1i, sx1[j]);
                    if (wi <= 0.0f) continue;
                    float hi = fminf(y2i, sy2[j]) - fmaxf(y1i, sy1[j]);
                    if (hi <= 0.0f) continue;
                    float inter = wi * hi;
                    float uni   = ai + aj - inter;
                    float we = fmaxf(x2i, sx2[j]) - fminf(x1i, sx1[j]);
                    float he = fmaxf(y2i, sy2[j]) - fminf(y1i, sy1[j]);
                    float ae = we * he;
                    float gf = __fdividef(inter, uni) - __fdividef(ae - uni, ae);
                    bool edge;
                    if (fabsf(gf - TBTH) > 3e-4f) {
                        edge = gf > TBTH;
                    } else {
                        float iou = inter / uni;       // bit-exact reference sequence
                        float q   = (ae - uni) / ae;
                        edge = (iou - q) > TBTH;
                    }
                    if (edge) {
                        int p = atomicAdd(&s_cnt, 1);
                        if (p < ECAP)
                            g_bedge[u * ECAP + p] = ((unsigned)i << 10) | (unsigned)j;
                    }
                }
            }
        }
        __threadfence();
        __syncthreads();
        if (tid == 0) {
            g_bcnt[u] = min(s_cnt, ECAP);
            __threadfence();
            int t = atomicAdd(&g_done[b], 1);
            s_last = (t == GB_PER_BATCH - 1);
            if (s_last) g_done[b] = 0;     // reset ticket for next graph replay
        }
        __syncthreads();
        if (!s_last) return;

        // -------- last block of batch: gather edges, CC, aggregation --------
        __threadfence();   // acquire: all batch edge data visible
        int*   lab   = (int*)(sbuf + 0);                       // 3600
        float* csum  = (float*)(sbuf + 3600);                  // 14400
        unsigned int* sedge = (unsigned int*)(sbuf + 3600);    // overlaps csum (dead after CC)
        float* ccnt  = (float*)(sbuf + 18000);                 // 3600
        short* mlist = (short*)(sbuf + 21600);                 // 512
        int*   scnt  = (int*)(sbuf + 22112);                   // 25 counts
        int*   coff  = scnt + GB_PER_BATCH;                    // 26 offsets

        for (int i = tid; i < NQ; i += 256) lab[i] = i;
        if (tid < GB_PER_BATCH) scnt[tid] = g_bcnt[b * GB_PER_BATCH + tid];
        __syncthreads();
        if (tid == 0) {
            int s = 0;
            #pragma unroll
            for (int k = 0; k < GB_PER_BATCH; k++) { coff[k] = s; s += scnt[k]; }
            coff[GB_PER_BATCH] = s;
        }
        __syncthreads();
        const int ne = min(coff[GB_PER_BATCH], MAXE);

        for (int e = tid; e < ne; e += 256) {
            int k = 0;
            #pragma unroll
            for (int t2 = 0; t2 < GB_PER_BATCH; t2++)
                if (e >= coff[t2 + 1]) k = t2 + 1;
            sedge[e] = g_bedge[(b * GB_PER_BATCH + k) * ECAP + (e - coff[k])];
        }
        __syncthreads();

        for (int it = 0; it < NQ; it++) {
            if (tid == 0) s_changed = 0;
            __syncthreads();
            for (int e = tid; e < ne; e += 256) {
                unsigned int pk = sedge[e];
                int i = pk >> 10, j = pk & 1023;
                int li = lab[i], lj = lab[j];
                int m = min(li, lj);
                if (li > m) { atomicMin(&lab[i], m); s_changed = 1; }
                if (lj > m) { atomicMin(&lab[j], m); s_changed = 1; }
            }
            __syncthreads();
            for (int i = tid; i < NQ; i += 256) {
                int l = lab[i], ll = lab[l];
                if (ll < l) { lab[i] = ll; s_changed = 1; }
            }
            __syncthreads();
            int ch = s_changed;
            __syncthreads();
            if (!ch) break;
        }

        // sedge dead from here; csum/ccnt initialize
        for (int i = tid; i < NQ; i += 256) {
            ccnt[i] = 0.0f;
            csum[4 * i + 0] = 0.0f; csum[4 * i + 1] = 0.0f;
            csum[4 * i + 2] = 0.0f; csum[4 * i + 3] = 0.0f;
        }
        __syncthreads();
        for (int i = tid; i < NQ; i += 256) {
            int l = lab[i];
            float4 bb = bboxes[b * NQ + i];
            atomicAdd(&ccnt[l], 1.0f);
            atomicAdd(&csum[4 * l + 0], bb.x);
            atomicAdd(&csum[4 * l + 1], bb.y);
            atomicAdd(&csum[4 * l + 2], bb.z);
            atomicAdd(&csum[4 * l + 3], bb.w);
        }
        __syncthreads();

        float4* oagg = (float4*)out;
        for (int i = tid; i < NQ; i += 256) {
            int l = lab[i];
            float d = ccnt[l] + 1e-6f;
            float4 o;
            o.x = csum[4 * l + 0] / d;
            o.y = csum[4 * l + 1] / d;
            o.z = csum[4 * l + 2] / d;
            o.w = csum[4 * l + 3] / d;
            oagg[b * NQ + i] = o;
            g_labels[b * NQ + i] = l;
            if (ccnt[l] > 1.5f) {
                int p = atomicAdd(&s_nm, 1);
                if (p < MAXM) mlist[p] = (short)i;
            }
        }
        __syncthreads();
        const int nm = min(s_nm, MAXM);
        for (int i = tid; i < nm; i += 256) g_mlist[b * MAXM + i] = mlist[i];
        if (tid == 0) g_nm[b] = nm;
    }
}

// ======================= K2: diag + off-diag patches (256 CTAs) =======================
#define K2_SLICES 8
__global__ void __launch_bounds__(256) k2(float* __restrict__ out) {
    const int b = blockIdx.x / K2_SLICES;
    const int s = blockIdx.x % K2_SLICES;
    const int tid = threadIdx.x;
    float* adj = out + ADJ_OFF_F;

    // diagonal 1.0s: ~113 rows per slice, one store per thread
    const int per = (NQ + K2_SLICES - 1) / K2_SLICES;   // 113
    const int i0 = s * per;
    const int i1 = min(i0 + per, NQ);
    for (int i = i0 + tid; i < i1; i += 256)
        adj[((size_t)(b * NQ + i)) * NQ + i] = 1.0f;

    // off-diagonal patches: slice 0 of each batch only
    if (s == 0) {
        __shared__ int sml[MAXM];
        __shared__ int slab[MAXM];
        const int nm = g_nm[b];
        for (int i = tid; i < nm; i += 256) {
            int q = g_mlist[b * MAXM + i];
            sml[i] = q;
            slab[i] = g_labels[b * NQ + q];
        }
        __syncthreads();
        for (int p = tid; p < nm * nm; p += 256) {
            int pa = p / nm, pc = p % nm;
            if (pa != pc && slab[pa] == slab[pc])
                adj[((size_t)(b * NQ + sml[pa])) * NQ + sml[pc]] = 1.0f;
        }
    }
}

extern "C" void kernel_launch(void* const* d_in, const int* in_sizes, int n_in,
                              void* d_out, int out_size) {
    const float4* bboxes = (const float4*)d_in[0];   // [32,900,4] fp32
    const float4* logits = (const float4*)d_in[1];   // [32,900,91] fp32
    float* out = (float*)d_out;                      // agg | logits | adj

    k1<<<K1_BLOCKS, 256>>>(bboxes, logits, out);
    k2<<<NB * K2_SLICES, 256>>>(out);
}